// round 13
// baseline (speedup 1.0000x reference)
#include <cuda_runtime.h>
#include <float.h>

// x: [B=64, N=4096, D=1024] fp32. Per (b,d): top-16 along N, then mean -> out [B, D].
// One thread per (b,d) column; warp lanes span consecutive d (coalesced 128B).
// Top-16 held sorted-descending in registers.
// Insert uses the level-parallel form new[j] = max(top[j], min(top[j-1], v)):
// all 16 levels independent (latency ~8 cyc) vs the serial bubble (~120 cyc),
// so the warp resumes issuing loads immediately after an insert.

#define B_DIM 64
#define N_DIM 4096
#define D_DIM 1024
#define K_TOP 16
#define NCOL (B_DIM * D_DIM)
#define TPB 64
#define U 16
#define NBATCH (N_DIM / U)   // 256

__device__ __forceinline__ void load_batch(float* __restrict__ buf,
                                           const float* __restrict__ p) {
#pragma unroll
    for (int u = 0; u < U; ++u)
        buf[u] = __ldcs(p + (size_t)u * D_DIM);
}

__device__ __forceinline__ void insert_parallel(float* __restrict__ top, float v) {
    // Precondition: v > top[K_TOP-1]. Sorted descending.
    float nt[K_TOP];
    nt[0] = fmaxf(top[0], v);
#pragma unroll
    for (int j = 1; j < K_TOP; ++j)
        nt[j] = fmaxf(top[j], fminf(top[j - 1], v));   // reads OLD top only
#pragma unroll
    for (int j = 0; j < K_TOP; ++j) top[j] = nt[j];
}

__device__ __forceinline__ void process_batch(float* __restrict__ top,
                                              const float* __restrict__ buf) {
#pragma unroll
    for (int u = 0; u < U; ++u) {
        float v = buf[u];
        if (v > top[K_TOP - 1]) {
            insert_parallel(top, v);
        }
    }
}

__global__ __launch_bounds__(TPB, 8)
void topk_mean_kernel(const float* __restrict__ x, float* __restrict__ out) {
    const int tid = blockIdx.x * TPB + threadIdx.x;
    const int b = tid >> 10;
    const int d = tid & 1023;

    const float* __restrict__ p = x + ((size_t)b * N_DIM) * D_DIM + d;

    float top[K_TOP];
#pragma unroll
    for (int j = 0; j < K_TOP; ++j) top[j] = -FLT_MAX;

    float bufA[U], bufB[U];

    // Preload batch 0.
    load_batch(bufA, p);
    p += (size_t)U * D_DIM;

    // Ping-pong: issue next batch's loads before consuming current batch.
#pragma unroll 1
    for (int pair = 0; pair < NBATCH / 2 - 1; ++pair) {
        load_batch(bufB, p);            // batch 2*pair+1
        p += (size_t)U * D_DIM;
        process_batch(top, bufA);
        load_batch(bufA, p);            // batch 2*pair+2
        p += (size_t)U * D_DIM;
        process_batch(top, bufB);
    }
    // Epilogue: batches 254, 255.
    load_batch(bufB, p);
    process_batch(top, bufA);
    process_batch(top, bufB);

    float s = 0.0f;
#pragma unroll
    for (int j = 0; j < K_TOP; ++j) s += top[j];
    out[tid] = s * (1.0f / K_TOP);
}

extern "C" void kernel_launch(void* const* d_in, const int* in_sizes, int n_in,
                              void* d_out, int out_size) {
    const float* x = (const float*)d_in[0];
    float* out = (float*)d_out;
    topk_mean_kernel<<<NCOL / TPB, TPB>>>(x, out);
}